// round 4
// baseline (speedup 1.0000x reference)
#include <cuda_runtime.h>
#include <math.h>
#include <stdint.h>

#define RAD   5
#define Bz    4
#define Ktok  4096
#define Cdim  256
#define Hdim  128
#define NTOK  (Bz*Ktok)           // 16384
#define IBLK  16                  // rows per weighted block
#define NWBLK (NTOK/IBLK)         // 1024 weighted blocks
#define WROWS 8                   // rows per weights block
#define NWTBLK (NTOK/WROWS)       // 2048 weights blocks

// ---------------- scratch ----------------
__device__ float  g_Tpart[256*Cdim];     // per-mlp-block (64-token chunk) col sums
__device__ float  g_e[NTOK];             // exp(s) per token

// ---------------- cp.async helpers ----------------
__device__ __forceinline__ uint32_t smem_u32(const void* p) {
    return (uint32_t)__cvta_generic_to_shared(p);
}
__device__ __forceinline__ void cp_async16(uint32_t dst, const void* src) {
    asm volatile("cp.async.ca.shared.global [%0], [%1], 16;" :: "r"(dst), "l"(src));
}
__device__ __forceinline__ void cp_commit() {
    asm volatile("cp.async.commit_group;");
}
__device__ __forceinline__ void cp_wait1() {
    asm volatile("cp.async.wait_group 1;");
}
__device__ __forceinline__ void cp_wait0() {
    asm volatile("cp.async.wait_group 0;");
}

// ---------------- MLP (8x8 microtile, pipelined) + colsum partials --------
// BM=64 tokens, BN=128 (full H), BK=16, 128 threads, each thread 8x8.
// A-tile prefetched via registers (transpose), B-tile double-buffered cp.async.
#define ASP 68   // padded As row stride (floats)
__global__ void __launch_bounds__(128, 4) k_mlp(const float* __restrict__ x,
                                                const float* __restrict__ W1,
                                                const float* __restrict__ b1,
                                                const float* __restrict__ W2,
                                                const float* __restrict__ b2) {
    __shared__ float As[16*ASP];       // [kk][token(64) pad 68]
    __shared__ float Bs[2][16*128];    // double-buffered [kk][hidden]
    __shared__ float sred[64];

    int tid = threadIdx.x;
    int tx = tid & 15;                 // hidden group: cols tx*8..tx*8+7
    int ty = tid >> 4;                 // token group: rows ty*8..ty*8+7
    int row0 = blockIdx.x * 64;

    // A-side slots: 2 float4/thread; idx=q*128+tid -> token=idx>>2, kq=(idx&3)<<2
    // B-side slots: 4 cp.async 16B/thread; idx=q*128+tid -> wk=idx>>5, wc=(idx&31)<<2

    float4 xg[2];
    #pragma unroll
    for (int q = 0; q < 2; q++) {
        int idx = q*128 + tid, token = idx >> 2, kq = (idx & 3) << 2;
        xg[q] = *(const float4*)&x[(size_t)(row0 + token)*Cdim + kq];
    }
    #pragma unroll
    for (int q = 0; q < 4; q++) {
        int idx = q*128 + tid, wk = idx >> 5, wc = (idx & 31) << 2;
        cp_async16(smem_u32(&Bs[0][wk*128 + wc]), &W1[(size_t)wk*Hdim + wc]);
    }
    cp_commit();

    float acc[8][8];
    #pragma unroll
    for (int i = 0; i < 8; i++)
        #pragma unroll
        for (int j = 0; j < 8; j++) acc[i][j] = 0.f;

    int it = 0;
    for (int kc = 0; kc < Cdim; kc += 16, it++) {
        int buf = it & 1;
        __syncthreads();               // previous compute done; As/Bs[buf^1] reusable
        // store A regs (chunk kc) to smem
        #pragma unroll
        for (int q = 0; q < 2; q++) {
            int idx = q*128 + tid, token = idx >> 2, kq = (idx & 3) << 2;
            As[(kq+0)*ASP + token] = xg[q].x;
            As[(kq+1)*ASP + token] = xg[q].y;
            As[(kq+2)*ASP + token] = xg[q].z;
            As[(kq+3)*ASP + token] = xg[q].w;
        }
        if (kc + 16 < Cdim) {
            // prefetch chunk kc+16: A via regs, B via cp.async into other buffer
            #pragma unroll
            for (int q = 0; q < 2; q++) {
                int idx = q*128 + tid, token = idx >> 2, kq = (idx & 3) << 2;
                xg[q] = *(const float4*)&x[(size_t)(row0 + token)*Cdim + kc + 16 + kq];
            }
            #pragma unroll
            for (int q = 0; q < 4; q++) {
                int idx = q*128 + tid, wk = idx >> 5, wc = (idx & 31) << 2;
                cp_async16(smem_u32(&Bs[buf^1][wk*128 + wc]),
                           &W1[(size_t)(kc + 16 + wk)*Hdim + wc]);
            }
            cp_commit();
            cp_wait1();                // Bs[buf] (older group) complete
        } else {
            cp_wait0();
        }
        __syncthreads();

        // fused column-sum partials: c = kc + (tid>>3), 8 lanes sum 8 tokens each
        {
            int cs_c = tid >> 3, cs_g = tid & 7;
            float4 a0 = *(const float4*)&As[cs_c*ASP + (cs_g << 3)];
            float4 a1 = *(const float4*)&As[cs_c*ASP + (cs_g << 3) + 4];
            float cs = ((a0.x+a0.y)+(a0.z+a0.w)) + ((a1.x+a1.y)+(a1.z+a1.w));
            #pragma unroll
            for (int off = 4; off >= 1; off >>= 1)
                cs += __shfl_down_sync(0xffffffffu, cs, off, 8);
            if (cs_g == 0)
                g_Tpart[(size_t)blockIdx.x * Cdim + kc + cs_c] = cs;
        }

        const float* Bp = Bs[buf];
        #pragma unroll
        for (int kk = 0; kk < 16; kk++) {
            float4 a0 = *(const float4*)&As[kk*ASP + (ty << 3)];
            float4 a1 = *(const float4*)&As[kk*ASP + (ty << 3) + 4];
            float4 b0 = *(const float4*)&Bp[kk*128 + (tx << 3)];
            float4 b1v = *(const float4*)&Bp[kk*128 + (tx << 3) + 4];
            float a[8]  = {a0.x, a0.y, a0.z, a0.w, a1.x, a1.y, a1.z, a1.w};
            float bb[8] = {b0.x, b0.y, b0.z, b0.w, b1v.x, b1v.y, b1v.z, b1v.w};
            #pragma unroll
            for (int i = 0; i < 8; i++)
                #pragma unroll
                for (int j = 0; j < 8; j++) acc[i][j] += a[i] * bb[j];
        }
    }

    // epilogue: h = tanh(acc + b1), s = sum_h h*W2[h], deterministic reduce
    float part[8] = {0.f,0.f,0.f,0.f,0.f,0.f,0.f,0.f};
    #pragma unroll
    for (int j = 0; j < 8; j++) {
        int hn = (tx << 3) + j;
        float b1j = b1[hn];
        float w2j = W2[hn];
        #pragma unroll
        for (int i = 0; i < 8; i++)
            part[i] += tanhf(acc[i][j] + b1j) * w2j;
    }
    #pragma unroll
    for (int off = 8; off >= 1; off >>= 1) {
        #pragma unroll
        for (int i = 0; i < 8; i++)
            part[i] += __shfl_down_sync(0xffffffffu, part[i], off, 16);
    }
    __syncthreads();
    if (tx == 0) {
        #pragma unroll
        for (int i = 0; i < 8; i++) sred[(ty << 3) + i] = part[i];
    }
    __syncthreads();
    if (tid < 64) {
        g_e[row0 + tid] = expf(sred[tid] + b2[0]);
    }
}

// ---------------- fused output: weighted + weights interleaved 1:2 --------
// No k_mid: each block derives 1/denom locally (same ascending-order sum ->
// bitwise identical across block types); weighted blocks self-reduce T.
__global__ void __launch_bounds__(256) k_fused(const float* __restrict__ x,
                                               float* __restrict__ wout,
                                               float* __restrict__ outw) {
    __shared__ float xs[(IBLK + 2*RAD) * Cdim];   // 26*256*4 = 26624 B
    __shared__ float sev[32];
    __shared__ float sinv[IBLK];

    int bid = blockIdx.x;              // 0..3071
    int tid = threadIdx.x;
    int g3 = bid % 3;
    int q  = bid / 3;                  // 0..1023

    if (g3 != 0) {
        // ---- weights fill: 8 rows per block, 128KB streamed store ----
        int chunk = q * 2 + (g3 - 1);             // 0..2047
        int r0 = chunk * WROWS;
        int b = r0 >> 12, i0 = r0 & (Ktok - 1);
        int jlo0 = max(i0 - RAD, 0);
        int jhi0 = min(i0 + WROWS - 1 + RAD, Ktok - 1);
        int n = jhi0 - jlo0 + 1;                  // <= 18
        if (tid < n) sev[tid] = g_e[((size_t)b << 12) + jlo0 + tid];
        __syncthreads();
        if (tid < WROWS) {
            int i = i0 + tid;
            int jlo = max(i - RAD, 0), jhi = min(i + RAD, Ktok - 1);
            float s = (float)(Ktok - (jhi - jlo + 1));
            for (int j = jlo; j <= jhi; j++) s += sev[j - jlo0];
            sinv[tid] = 1.0f / s;
        }
        __syncthreads();

        #pragma unroll
        for (int ii = 0; ii < WROWS; ii++) {
            int i = i0 + ii;
            float inv = sinv[ii];
            int jlo = max(i - RAD, 0), jhi = min(i + RAD, Ktok - 1);
            float* row = wout + (size_t)(r0 + ii) * Ktok;
            float4 v4 = make_float4(inv, inv, inv, inv);
            #pragma unroll
            for (int q2 = 0; q2 < 4; q2++) {
                int jj = (q2 << 10) + (tid << 2);
                float4 t = v4;
                if (jj + 3 >= jlo && jj <= jhi) {
                    if (jj + 0 >= jlo && jj + 0 <= jhi) t.x = sev[jj + 0 - jlo0] * inv;
                    if (jj + 1 >= jlo && jj + 1 <= jhi) t.y = sev[jj + 1 - jlo0] * inv;
                    if (jj + 2 >= jlo && jj + 2 <= jhi) t.z = sev[jj + 2 - jlo0] * inv;
                    if (jj + 3 >= jlo && jj + 3 <= jhi) t.w = sev[jj + 3 - jlo0] * inv;
                }
                __stcs((float4*)&row[jj], t);
            }
        }
    } else {
        // ---- weighted: out[i,:] = (T + sum_band (e_j-1) x_j) * inv_i ----
        int b = q >> 8;                           // 256 blocks per batch
        int i0 = (q & 255) << 4;                  // row base within batch
        int jlo = max(i0 - RAD, 0);
        int jhi = min(i0 + IBLK - 1 + RAD, Ktok - 1);
        int n = jhi - jlo + 1;                    // <= 26

        const float* xb = x + (((size_t)b << 12) + jlo) * Cdim;
        for (int idx = tid; idx < n * Cdim; idx += 256)
            xs[idx] = xb[idx];
        if (tid < n) sev[tid] = g_e[((size_t)b << 12) + jlo + tid];
        __syncthreads();

        // local 1/denom for my 16 rows (same ascending order as weights blocks)
        if (tid < IBLK) {
            int i = i0 + tid;
            int jl = max(i - RAD, 0), jh = min(i + RAD, Ktok - 1);
            float s = (float)(Ktok - (jh - jl + 1));
            for (int j = jl; j <= jh; j++) s += sev[j - jlo];
            sinv[tid] = 1.0f / s;
        }
        // self-reduce T for my channel c = tid (deterministic fixed order)
        double Td = 0.0;
        #pragma unroll
        for (int ch = 0; ch < 64; ch++)
            Td += (double)g_Tpart[(size_t)(b*64 + ch)*Cdim + tid];
        float Tc = (float)Td;
        __syncthreads();
        if (tid < n) sev[tid] -= 1.0f;            // e-1 for the numerator
        __syncthreads();

        int c = tid;
        float* op = outw + (((size_t)b << 12) + i0) * Cdim + c;
        #pragma unroll
        for (int ii = 0; ii < IBLK; ii++) {
            int i = i0 + ii;
            int lo = max(i - RAD, 0) - jlo;
            int hi = min(i + RAD, Ktok - 1) - jlo;
            float acc = Tc;
            for (int r = lo; r <= hi; r++) acc += sev[r] * xs[r * Cdim + c];
            __stcs(&op[(size_t)ii * Cdim], acc * sinv[ii]);
        }
    }
}

// ---------------- launch ----------------
extern "C" void kernel_launch(void* const* d_in, const int* in_sizes, int n_in,
                              void* d_out, int out_size) {
    (void)in_sizes; (void)n_in; (void)out_size;
    const float* x  = (const float*)d_in[0];
    const float* W1 = (const float*)d_in[1];
    const float* b1 = (const float*)d_in[2];
    const float* W2 = (const float*)d_in[3];
    const float* b2 = (const float*)d_in[4];

    float* out_weighted = (float*)d_out;                          // [B,K,C]
    float* out_weights  = (float*)d_out + (size_t)NTOK * Cdim;    // [B,K,K]

    k_mlp  <<<NTOK / 64,      128>>>(x, W1, b1, W2, b2);
    k_fused<<<NWBLK + NWTBLK, 256>>>(x, out_weights, out_weighted);
}

// round 5
// speedup vs baseline: 1.3254x; 1.3254x over previous
#include <cuda_runtime.h>
#include <math.h>
#include <stdint.h>

#define RAD    5
#define Bz     4
#define Ktok   4096
#define Cdim   256
#define Hdim   128
#define NTOK   (Bz*Ktok)          // 16384
#define TTOK   16                 // tokens per MLP tile
#define NMLP   (NTOK/TTOK)        // 1024 MLP blocks
#define WROWS  4                  // rows per weights block
#define NWT    (NTOK/WROWS)       // 4096 weights blocks
#define IBW    8                  // rows per weighted block
#define NWD    (NTOK/IBW)         // 2048 weighted blocks
#define NBLK   (NMLP + NWT + NWD) // 7168

// ---------------- scratch + flags ----------------
__device__ float  g_Tpart[NMLP*Cdim];    // per-tile column sums
__device__ float  g_T[Bz*Cdim];          // final per-batch column sums
__device__ float  g_e[NTOK];             // exp(s) per token
__device__ volatile int g_ready[NMLP];   // per-tile e ready
__device__ int          g_done;          // mlp completion counter
__device__ volatile int g_tready;        // g_T ready

__global__ void k_reset() {
    int tid = threadIdx.x;
    for (int i = tid; i < NMLP; i += 128) g_ready[i] = 0;
    if (tid == 0) { g_done = 0; g_tready = 0; }
}

// ---------------- mega kernel ----------------
// smem padded to 48KB to cap occupancy (force progressive MLP waves)
#define SMEM_BYTES 49152
#define ASP2 17

__global__ void __launch_bounds__(128) k_all(const float* __restrict__ x,
                                             const float* __restrict__ W1,
                                             const float* __restrict__ b1,
                                             const float* __restrict__ W2,
                                             const float* __restrict__ b2,
                                             float* __restrict__ wout,
                                             float* __restrict__ outw) {
    __shared__ __align__(16) char smem_raw[SMEM_BYTES];
    int bid = blockIdx.x;
    int tid = threadIdx.x;

    if (bid < NMLP) {
        // ================= MLP tile: 16 tokens x 128 hidden, C=256 =========
        float* As   = (float*)smem_raw;            // [16 kk][17] = 1088B
        float* Bsm  = As + 16*ASP2;                // [16][128]   = 8KB
        float* sred = Bsm + 16*128;                // [16]
        int*  s_last = (int*)(smem_raw + SMEM_BYTES - 16);

        int row0 = bid * TTOK;
        int tx = tid & 15;           // hidden cols tx*8..+7
        int ty = tid >> 4;           // rows {ty, ty+8}

        float acc[2][8];
        #pragma unroll
        for (int i = 0; i < 2; i++)
            #pragma unroll
            for (int j = 0; j < 8; j++) acc[i][j] = 0.f;

        for (int kc = 0; kc < Cdim; kc += 16) {
            __syncthreads();
            if (tid < 64) {
                int token = tid >> 2, kq = (tid & 3) << 2;
                float4 xg = *(const float4*)&x[(size_t)(row0 + token)*Cdim + kc + kq];
                As[(kq+0)*ASP2 + token] = xg.x;
                As[(kq+1)*ASP2 + token] = xg.y;
                As[(kq+2)*ASP2 + token] = xg.z;
                As[(kq+3)*ASP2 + token] = xg.w;
            }
            #pragma unroll
            for (int q = 0; q < 4; q++) {
                int idx = q*128 + tid, wk = idx >> 5, wc = (idx & 31) << 2;
                *(float4*)&Bsm[wk*128 + wc] =
                    *(const float4*)&W1[(size_t)(kc + wk)*Hdim + wc];
            }
            __syncthreads();

            // column-sum partial: c = kc + (tid>>3); lanes tid&7 sum 2 tokens
            {
                int cs_c = tid >> 3, cs_g = tid & 7;
                float cs = As[cs_c*ASP2 + 2*cs_g] + As[cs_c*ASP2 + 2*cs_g + 1];
                #pragma unroll
                for (int off = 4; off >= 1; off >>= 1)
                    cs += __shfl_down_sync(0xffffffffu, cs, off, 8);
                if (cs_g == 0)
                    g_Tpart[(size_t)bid*Cdim + kc + cs_c] = cs;
            }

            #pragma unroll
            for (int kk = 0; kk < 16; kk++) {
                float a0 = As[kk*ASP2 + ty];
                float a1 = As[kk*ASP2 + ty + 8];
                float4 b0 = *(const float4*)&Bsm[kk*128 + (tx << 3)];
                float4 b1v = *(const float4*)&Bsm[kk*128 + (tx << 3) + 4];
                float bb[8] = {b0.x,b0.y,b0.z,b0.w,b1v.x,b1v.y,b1v.z,b1v.w};
                #pragma unroll
                for (int j = 0; j < 8; j++) {
                    acc[0][j] += a0 * bb[j];
                    acc[1][j] += a1 * bb[j];
                }
            }
        }

        // epilogue: tanh, @W2, reduce over tx, exp
        float part[2] = {0.f, 0.f};
        #pragma unroll
        for (int j = 0; j < 8; j++) {
            int hn = (tx << 3) + j;
            float b1j = b1[hn], w2j = W2[hn];
            part[0] += tanhf(acc[0][j] + b1j) * w2j;
            part[1] += tanhf(acc[1][j] + b1j) * w2j;
        }
        #pragma unroll
        for (int off = 8; off >= 1; off >>= 1) {
            part[0] += __shfl_down_sync(0xffffffffu, part[0], off, 16);
            part[1] += __shfl_down_sync(0xffffffffu, part[1], off, 16);
        }
        __syncthreads();
        if (tx == 0) { sred[ty] = part[0]; sred[ty + 8] = part[1]; }
        __syncthreads();
        if (tid < TTOK)
            g_e[row0 + tid] = expf(sred[tid] + b2[0]);

        // publish tile
        __threadfence();
        __syncthreads();
        if (tid == 0) {
            g_ready[bid] = 1;
            int old = atomicAdd(&g_done, 1);
            *s_last = (old == NMLP - 1);
        }
        __syncthreads();
        if (*s_last) {
            // reduce T (fp32, fixed order, one block only)
            for (int o = tid; o < Bz*Cdim; o += 128) {
                int b = o >> 8, c = o & 255;
                float s = 0.f;
                for (int t = 0; t < NMLP/Bz; t++)
                    s += g_Tpart[(size_t)(b*(NMLP/Bz) + t)*Cdim + c];
                g_T[o] = s;
            }
            __threadfence();
            __syncthreads();
            if (tid == 0) g_tready = 1;
        }

    } else if (bid < NMLP + NWT) {
        // ================= weights rows: 4 rows, 64KB streamed =============
        float* sev  = (float*)smem_raw;            // [16]
        float* sinv = sev + 16;                    // [4]

        int chunk = bid - NMLP;                    // 0..4095
        int r0 = chunk * WROWS;
        int b = r0 >> 12, i0 = r0 & (Ktok - 1);
        int jlo0 = max(i0 - RAD, 0);
        int jhi0 = min(i0 + WROWS - 1 + RAD, Ktok - 1);
        int n = jhi0 - jlo0 + 1;                   // <= 14
        int tlo = (((b << 12) + jlo0) >> 4);
        int thi = (((b << 12) + jhi0) >> 4);

        if (tid == 0) {
            while (g_ready[tlo] == 0 || g_ready[thi] == 0) __nanosleep(64);
        }
        __syncthreads();
        __threadfence();

        if (tid < n) sev[tid] = __ldcg(&g_e[((size_t)b << 12) + jlo0 + tid]);
        __syncthreads();
        if (tid < WROWS) {
            int i = i0 + tid;
            int jl = max(i - RAD, 0), jh = min(i + RAD, Ktok - 1);
            float s = (float)(Ktok - (jh - jl + 1));
            for (int j = jl; j <= jh; j++) s += sev[j - jlo0];
            sinv[tid] = 1.0f / s;
        }
        __syncthreads();

        #pragma unroll
        for (int ii = 0; ii < WROWS; ii++) {
            int i = i0 + ii;
            float inv = sinv[ii];
            int jl = max(i - RAD, 0), jh = min(i + RAD, Ktok - 1);
            float* row = wout + (size_t)(r0 + ii) * Ktok;
            float4 v4 = make_float4(inv, inv, inv, inv);
            #pragma unroll
            for (int q2 = 0; q2 < 8; q2++) {
                int jj = (q2 << 9) + (tid << 2);
                float4 t = v4;
                if (jj + 3 >= jl && jj <= jh) {
                    if (jj + 0 >= jl && jj + 0 <= jh) t.x = sev[jj + 0 - jlo0] * inv;
                    if (jj + 1 >= jl && jj + 1 <= jh) t.y = sev[jj + 1 - jlo0] * inv;
                    if (jj + 2 >= jl && jj + 2 <= jh) t.z = sev[jj + 2 - jlo0] * inv;
                    if (jj + 3 >= jl && jj + 3 <= jh) t.w = sev[jj + 3 - jlo0] * inv;
                }
                __stcs((float4*)&row[jj], t);
            }
        }

    } else {
        // ================= weighted: 8 rows, band accumulate ===============
        float* xs   = (float*)smem_raw;            // [18][256] = 18432B
        float* em1  = xs + (IBW + 2*RAD) * Cdim;   // [18]
        float* sinv = em1 + 18;                    // [8]

        int q = bid - NMLP - NWT;                  // 0..2047
        int b = q >> 9;                            // 512 blocks per batch
        int i0 = (q & 511) << 3;
        int jlo = max(i0 - RAD, 0);
        int jhi = min(i0 + IBW - 1 + RAD, Ktok - 1);
        int n = jhi - jlo + 1;                     // <= 18

        if (tid == 0) {
            while (g_tready == 0) __nanosleep(128);
        }
        __syncthreads();
        __threadfence();

        const float* xb = x + (((size_t)b << 12) + jlo) * Cdim;
        for (int idx = tid; idx < n * Cdim; idx += 128)
            xs[idx] = xb[idx];
        if (tid < n) em1[tid] = __ldcg(&g_e[((size_t)b << 12) + jlo + tid]);
        __syncthreads();
        if (tid < IBW) {
            int i = i0 + tid;
            int jl = max(i - RAD, 0), jh = min(i + RAD, Ktok - 1);
            float s = (float)(Ktok - (jh - jl + 1));
            for (int j = jl; j <= jh; j++) s += em1[j - jlo];
            sinv[tid] = 1.0f / s;
        }
        __syncthreads();
        if (tid < n) em1[tid] -= 1.0f;
        float Tc0 = __ldcg(&g_T[b * Cdim + tid]);
        float Tc1 = __ldcg(&g_T[b * Cdim + tid + 128]);
        __syncthreads();

        float* op = outw + (((size_t)b << 12) + i0) * Cdim;
        #pragma unroll
        for (int ii = 0; ii < IBW; ii++) {
            int i = i0 + ii;
            int lo = max(i - RAD, 0) - jlo;
            int hi = min(i + RAD, Ktok - 1) - jlo;
            float a0 = Tc0, a1 = Tc1;
            for (int r = lo; r <= hi; r++) {
                float f = em1[r];
                a0 += f * xs[r * Cdim + tid];
                a1 += f * xs[r * Cdim + tid + 128];
            }
            float inv = sinv[ii];
            __stcs(&op[(size_t)ii * Cdim + tid],        a0 * inv);
            __stcs(&op[(size_t)ii * Cdim + tid + 128],  a1 * inv);
        }
    }
}

// ---------------- launch ----------------
extern "C" void kernel_launch(void* const* d_in, const int* in_sizes, int n_in,
                              void* d_out, int out_size) {
    (void)in_sizes; (void)n_in; (void)out_size;
    const float* x  = (const float*)d_in[0];
    const float* W1 = (const float*)d_in[1];
    const float* b1 = (const float*)d_in[2];
    const float* W2 = (const float*)d_in[3];
    const float* b2 = (const float*)d_in[4];

    float* out_weighted = (float*)d_out;                          // [B,K,C]
    float* out_weights  = (float*)d_out + (size_t)NTOK * Cdim;    // [B,K,K]

    k_reset<<<1, 128>>>();
    k_all<<<NBLK, 128>>>(x, W1, b1, W2, b2, out_weights, out_weighted);
}

// round 6
// speedup vs baseline: 2.1736x; 1.6400x over previous
#include <cuda_runtime.h>
#include <math.h>
#include <stdint.h>

#define RAD   5
#define Bz    4
#define Ktok  4096
#define Cdim  256
#define Hdim  128
#define NTOK  (Bz*Ktok)           // 16384
#define IBLK  16                  // rows per weighted block
#define NWBLK (NTOK/IBLK)         // 1024 weighted blocks
#define WROWS 8                   // rows per weights block
#define NWTBLK (NTOK/WROWS)       // 2048 weights blocks

// ---------------- scratch ----------------
__device__ float  g_Tpart[256*Cdim];     // per-mlp-block (64-token chunk) col sums
__device__ float  g_T[Bz*Cdim];          // final per-batch column sums
__device__ float  g_e[NTOK];             // exp(s) per token
__device__ float  g_inv[NTOK];           // 1/denom per row

// packed f32x2 helpers
__device__ __forceinline__ void ffma2(uint64_t& d, uint64_t a, uint64_t b) {
    asm volatile("fma.rn.f32x2 %0, %1, %2, %0;" : "+l"(d) : "l"(a), "l"(b));
}
__device__ __forceinline__ uint64_t pack2(float v) {
    uint64_t r;
    asm("mov.b64 %0, {%1, %1};" : "=l"(r) : "r"(__float_as_uint(v)));
    return r;
}

// ---------------- MLP (8 tok x 4 f32x2-pair microtile) + colsum ----------
// BM=64 tokens, BN=128 (full H), BK=16, 128 threads.
#define ASP 68   // padded As row stride (floats)
__global__ void __launch_bounds__(128, 4) k_mlp(const float* __restrict__ x,
                                                const float* __restrict__ W1,
                                                const float* __restrict__ b1,
                                                const float* __restrict__ W2,
                                                const float* __restrict__ b2) {
    __shared__ float As[16*ASP];     // [kk][token(64) pad 68]
    __shared__ float Bs[16*128];     // [kk][hidden]
    __shared__ float sred[64];

    int tid = threadIdx.x;
    int tx = tid & 15;               // hidden group: cols tx*8..tx*8+7 (4 pairs)
    int ty = tid >> 4;               // token group: rows ty*8..ty*8+7
    int row0 = blockIdx.x * 64;

    uint64_t acc[8][4];              // [token][hidden-pair], each f32x2
    #pragma unroll
    for (int i = 0; i < 8; i++)
        #pragma unroll
        for (int p = 0; p < 4; p++) acc[i][p] = 0ull;

    for (int kc = 0; kc < Cdim; kc += 16) {
        __syncthreads();
        // fill As: 64 tokens x 16 k = 256 float4, 2 per thread (transpose)
        #pragma unroll
        for (int q = 0; q < 2; q++) {
            int idx = q * 128 + tid;
            int token = idx >> 2;
            int kq = (idx & 3) << 2;
            float4 xg = *(const float4*)&x[(size_t)(row0 + token)*Cdim + kc + kq];
            As[(kq+0)*ASP + token] = xg.x;
            As[(kq+1)*ASP + token] = xg.y;
            As[(kq+2)*ASP + token] = xg.z;
            As[(kq+3)*ASP + token] = xg.w;
        }
        // fill Bs: 16 k x 128 hidden = 512 float4, 4 per thread
        #pragma unroll
        for (int q = 0; q < 4; q++) {
            int idx = q * 128 + tid;
            int wk = idx >> 5;
            int wc = (idx & 31) << 2;
            *(float4*)&Bs[wk*128 + wc] = *(const float4*)&W1[(size_t)(kc + wk)*Hdim + wc];
        }
        __syncthreads();

        // fused column-sum partials: c = kc + (tid>>3), 8 lanes sum 8 tokens each
        {
            int cs_c = tid >> 3;
            int cs_g = tid & 7;
            float4 a0 = *(const float4*)&As[cs_c*ASP + (cs_g << 3)];
            float4 a1 = *(const float4*)&As[cs_c*ASP + (cs_g << 3) + 4];
            float cs = ((a0.x+a0.y)+(a0.z+a0.w)) + ((a1.x+a1.y)+(a1.z+a1.w));
            #pragma unroll
            for (int off = 4; off >= 1; off >>= 1)
                cs += __shfl_down_sync(0xffffffffu, cs, off, 8);
            if (cs_g == 0)
                g_Tpart[(size_t)blockIdx.x * Cdim + kc + cs_c] = cs;
        }

        #pragma unroll
        for (int kk = 0; kk < 16; kk++) {
            // a: 8 token scalars -> packed duplicates
            float4 a0 = *(const float4*)&As[kk*ASP + (ty << 3)];
            float4 a1 = *(const float4*)&As[kk*ASP + (ty << 3) + 4];
            uint64_t ap[8];
            ap[0] = pack2(a0.x); ap[1] = pack2(a0.y);
            ap[2] = pack2(a0.z); ap[3] = pack2(a0.w);
            ap[4] = pack2(a1.x); ap[5] = pack2(a1.y);
            ap[6] = pack2(a1.z); ap[7] = pack2(a1.w);
            // b: 4 natural f32x2 pairs from two 16B loads
            ulonglong2 bq0 = *(const ulonglong2*)&Bs[kk*128 + (tx << 3)];
            ulonglong2 bq1 = *(const ulonglong2*)&Bs[kk*128 + (tx << 3) + 4];
            uint64_t bp[4] = {bq0.x, bq0.y, bq1.x, bq1.y};
            #pragma unroll
            for (int i = 0; i < 8; i++)
                #pragma unroll
                for (int p = 0; p < 4; p++)
                    ffma2(acc[i][p], ap[i], bp[p]);
        }
    }

    // epilogue: unpack, h = tanh(acc + b1), s = sum_h h*W2[h], reduce over tx
    float part[8] = {0.f,0.f,0.f,0.f,0.f,0.f,0.f,0.f};
    #pragma unroll
    for (int p = 0; p < 4; p++) {
        int hn0 = (tx << 3) + 2*p;
        float b1a = b1[hn0],     w2a = W2[hn0];
        float b1b = b1[hn0 + 1], w2b = W2[hn0 + 1];
        #pragma unroll
        for (int i = 0; i < 8; i++) {
            float lo = __uint_as_float((unsigned)(acc[i][p] & 0xffffffffu));
            float hi = __uint_as_float((unsigned)(acc[i][p] >> 32));
            part[i] += tanhf(lo + b1a) * w2a;
            part[i] += tanhf(hi + b1b) * w2b;
        }
    }
    #pragma unroll
    for (int off = 8; off >= 1; off >>= 1) {
        #pragma unroll
        for (int i = 0; i < 8; i++)
            part[i] += __shfl_down_sync(0xffffffffu, part[i], off, 16);
    }
    __syncthreads();
    if (tx == 0) {
        #pragma unroll
        for (int i = 0; i < 8; i++) sred[(ty << 3) + i] = part[i];
    }
    __syncthreads();
    if (tid < 64) {
        g_e[row0 + tid] = expf(sred[tid] + b2[0]);
    }
}

// ---------------- mid: reduce T + compute 1/denom ----------------
__global__ void __launch_bounds__(256) k_mid() {
    int bid = blockIdx.x;
    int tid = threadIdx.x;
    if (bid < 4) {
        int b = bid, c = tid;
        double s = 0.0;
        #pragma unroll
        for (int ch = 0; ch < 64; ch++)
            s += (double)g_Tpart[(size_t)(b*64 + ch)*Cdim + c];
        g_T[b*Cdim + c] = (float)s;
    } else {
        int g = (bid - 4) * 256 + tid;        // 0..16383
        int b = g >> 12;
        int i = g & (Ktok - 1);
        int jlo = max(i - RAD, 0), jhi = min(i + RAD, Ktok - 1);
        float s = (float)(Ktok - (jhi - jlo + 1));
        const float* ep = g_e + ((size_t)b << 12);
        #pragma unroll
        for (int j = 0; j < 2*RAD + 1; j++) {
            int jj = jlo + j;
            if (jj <= jhi) s += ep[jj];
        }
        g_inv[g] = 1.0f / s;
    }
}

// ---------------- fused output: weighted + weights interleaved 1:2 --------
__global__ void __launch_bounds__(256) k_fused(const float* __restrict__ x,
                                               float* __restrict__ wout,
                                               float* __restrict__ outw) {
    __shared__ float xs[(IBLK + 2*RAD) * Cdim];   // 26*256*4 = 26624 B (reused)
    __shared__ float em1[32];
    __shared__ float invs[IBLK];

    int bid = blockIdx.x;              // 0..3071
    int tid = threadIdx.x;
    int g3 = bid % 3;
    int q  = bid / 3;                  // 0..1023

    if (g3 != 0) {
        // ---- weights fill: 8 rows per block, 128KB streamed store ----
        int chunk = q * 2 + (g3 - 1);             // 0..2047
        int r0 = chunk * WROWS;
        int b = r0 >> 12, i0 = r0 & (Ktok - 1);
        int jlo0 = max(i0 - RAD, 0);
        int jhi0 = min(i0 + WROWS - 1 + RAD, Ktok - 1);
        int n = jhi0 - jlo0 + 1;                  // <= 18
        float* sev  = xs;                          // reuse smem
        float* sinv = xs + 32;
        if (tid < n)     sev[tid]  = g_e[((size_t)b << 12) + jlo0 + tid];
        if (tid < WROWS) sinv[tid] = g_inv[r0 + tid];
        __syncthreads();

        #pragma unroll
        for (int ii = 0; ii < WROWS; ii++) {
            int i = i0 + ii;
            float inv = sinv[ii];
            int jlo = max(i - RAD, 0), jhi = min(i + RAD, Ktok - 1);
            float* row = wout + (size_t)(r0 + ii) * Ktok;
            float4 v4 = make_float4(inv, inv, inv, inv);
            #pragma unroll
            for (int q2 = 0; q2 < 4; q2++) {
                int jj = (q2 << 10) + (tid << 2);
                float4 t = v4;
                if (jj + 3 >= jlo && jj <= jhi) {
                    if (jj + 0 >= jlo && jj + 0 <= jhi) t.x = sev[jj + 0 - jlo0] * inv;
                    if (jj + 1 >= jlo && jj + 1 <= jhi) t.y = sev[jj + 1 - jlo0] * inv;
                    if (jj + 2 >= jlo && jj + 2 <= jhi) t.z = sev[jj + 2 - jlo0] * inv;
                    if (jj + 3 >= jlo && jj + 3 <= jhi) t.w = sev[jj + 3 - jlo0] * inv;
                }
                __stcs((float4*)&row[jj], t);
            }
        }
    } else {
        // ---- weighted: out[i,:] = (T + sum_band (e_j-1) x_j) * inv_i ----
        int b = q >> 8;                           // 256 blocks per batch
        int i0 = (q & 255) << 4;                  // row base within batch
        int jlo = max(i0 - RAD, 0);
        int jhi = min(i0 + IBLK - 1 + RAD, Ktok - 1);
        int n = jhi - jlo + 1;                    // <= 26

        const float* xb = x + (((size_t)b << 12) + jlo) * Cdim;
        for (int idx = tid; idx < n * Cdim; idx += 256)
            xs[idx] = xb[idx];
        if (tid < n)    em1[tid]  = g_e[((size_t)b << 12) + jlo + tid] - 1.0f;
        if (tid < IBLK) invs[tid] = g_inv[((size_t)b << 12) + i0 + tid];
        float Tc = g_T[b * Cdim + tid];
        __syncthreads();

        int c = tid;
        float* op = outw + (((size_t)b << 12) + i0) * Cdim + c;
        #pragma unroll
        for (int ii = 0; ii < IBLK; ii++) {
            int i = i0 + ii;
            int lo = max(i - RAD, 0) - jlo;
            int hi = min(i + RAD, Ktok - 1) - jlo;
            float acc = Tc;
            for (int r = lo; r <= hi; r++) acc += em1[r] * xs[r * Cdim + c];
            __stcs(&op[(size_t)ii * Cdim], acc * invs[ii]);
        }
    }
}

// ---------------- launch ----------------
extern "C" void kernel_launch(void* const* d_in, const int* in_sizes, int n_in,
                              void* d_out, int out_size) {
    (void)in_sizes; (void)n_in; (void)out_size;
    const float* x  = (const float*)d_in[0];
    const float* W1 = (const float*)d_in[1];
    const float* b1 = (const float*)d_in[2];
    const float* W2 = (const float*)d_in[3];
    const float* b2 = (const float*)d_in[4];

    float* out_weighted = (float*)d_out;                          // [B,K,C]
    float* out_weights  = (float*)d_out + (size_t)NTOK * Cdim;    // [B,K,K]

    k_mlp  <<<NTOK / 64,       128>>>(x, W1, b1, W2, b2);
    k_mid  <<<4 + NTOK / 256,  256>>>();
    k_fused<<<NWBLK + NWTBLK,  256>>>(x, out_weights, out_weighted);
}

// round 8
// speedup vs baseline: 2.6626x; 1.2249x over previous
#include <cuda_runtime.h>
#include <cuda_bf16.h>
#include <math.h>
#include <stdint.h>

#define RAD   5
#define Bz    4
#define Ktok  4096
#define Cdim  256
#define Hdim  128
#define NTOK  (Bz*Ktok)           // 16384
#define IBLK  16                  // rows per weighted block
#define NWBLK (NTOK/IBLK)         // 1024 weighted blocks
#define WROWS 8                   // rows per weights block
#define NWTBLK (NTOK/WROWS)       // 2048 weights blocks
#define NMMA  (NTOK/128)          // 128 MMA CTAs

// ---------------- scratch ----------------
__device__ float  g_Tpart[NMMA*Cdim];    // per-CTA (128-token) col sums
__device__ float  g_T[Bz*Cdim];
__device__ float  g_e[NTOK];
__device__ float  g_inv[NTOK];

// ---------------- warp-mma helpers (plain sm_80+ PTX, no tcgen05) --------
__device__ __forceinline__ uint32_t smem_u32(const void* p) {
    return (uint32_t)__cvta_generic_to_shared(p);
}
#define LDSM4(r0, r1, r2, r3, addr) \
    asm volatile("ldmatrix.sync.aligned.m8n8.x4.shared.b16 {%0,%1,%2,%3}, [%4];" \
        : "=r"(r0), "=r"(r1), "=r"(r2), "=r"(r3) : "r"(addr))
#define MMA16816(d, a, b) \
    asm volatile("mma.sync.aligned.m16n8k16.row.col.f32.bf16.bf16.f32 " \
        "{%0,%1,%2,%3}, {%4,%5,%6,%7}, {%8,%9}, {%0,%1,%2,%3};" \
        : "+f"((d)[0]), "+f"((d)[1]), "+f"((d)[2]), "+f"((d)[3]) \
        : "r"((a)[0]), "r"((a)[1]), "r"((a)[2]), "r"((a)[3]), \
          "r"((b)[0]), "r"((b)[1]))

__device__ __forceinline__ uint64_t pk4(__nv_bfloat16 a, __nv_bfloat16 b,
                                        __nv_bfloat16 c, __nv_bfloat16 d) {
    uint16_t ua = *(uint16_t*)&a, ub = *(uint16_t*)&b;
    uint16_t uc = *(uint16_t*)&c, ud = *(uint16_t*)&d;
    return (uint64_t)ua | ((uint64_t)ub << 16) | ((uint64_t)uc << 32) | ((uint64_t)ud << 48);
}
__device__ __forceinline__ void split_bf16(float v, __nv_bfloat16& h, __nv_bfloat16& l) {
    h = __float2bfloat16(v);
    l = __float2bfloat16(v - __bfloat162float(h));
}

// ---------------- MLP via warp-mma bf16 split x3 + colsum ----------------
// Per CTA: 128 tokens(M) x 128 hidden(N), K=256 in 8 chunks of 32.
// 8 warps: 4(M) x 2(N); warp tile 32x64. Tiles: 64B rows, swizzle ^((row&7)<<4).
__global__ void __launch_bounds__(256, 1)
k_mma(const float* __restrict__ x, const float* __restrict__ W1,
      const float* __restrict__ b1, const float* __restrict__ W2,
      const float* __restrict__ b2) {
    __shared__ __align__(16) char Ah[128*64];   // 8KB each
    __shared__ __align__(16) char Al[128*64];
    __shared__ __align__(16) char Bh[128*64];
    __shared__ __align__(16) char Bl[128*64];
    __shared__ float4 sredc[8][8];
    __shared__ float  sredE[128][2];
    __shared__ float  b1s[Hdim], w2s[Hdim];

    int tid = threadIdx.x;
    int wid = tid >> 5, lane = tid & 31;
    int wm = wid & 3, wn = wid >> 2;     // 4 M-warps x 2 N-warps
    int m0 = blockIdx.x * 128;

    if (tid < Hdim) { b1s[tid] = b1[tid]; w2s[tid] = W2[tid]; }

    uint32_t ah_b = smem_u32(Ah), al_b = smem_u32(Al);
    uint32_t bh_b = smem_u32(Bh), bl_b = smem_u32(Bl);

    float acc[2][8][4];
    #pragma unroll
    for (int mf = 0; mf < 2; mf++)
        #pragma unroll
        for (int nf = 0; nf < 8; nf++)
            #pragma unroll
            for (int c = 0; c < 4; c++) acc[mf][nf][c] = 0.f;

    for (int ck = 0; ck < 8; ck++) {
        int kc = ck * 32;
        __syncthreads();   // previous chunk compute done; tiles reusable

        // ---- A conversion (x fp32 -> bf16 hi/lo) + colsum partial ----
        {
            float4 ps = make_float4(0.f, 0.f, 0.f, 0.f);
            int f8 = tid & 7;                 // float4 slot in 32-k row
            #pragma unroll
            for (int q = 0; q < 4; q++) {
                int row = q * 32 + (tid >> 3);
                float4 v = *(const float4*)&x[(size_t)(m0 + row)*Cdim + kc + f8*4];
                ps.x += v.x; ps.y += v.y; ps.z += v.z; ps.w += v.w;
                __nv_bfloat16 h0,l0,h1,l1,h2,l2,h3,l3;
                split_bf16(v.x, h0, l0); split_bf16(v.y, h1, l1);
                split_bf16(v.z, h2, l2); split_bf16(v.w, h3, l3);
                uint32_t off = (uint32_t)(row * 64 + f8 * 8);
                uint32_t sw = off ^ (((uint32_t)(row & 7)) << 4);
                *(uint64_t*)(Ah + sw) = pk4(h0, h1, h2, h3);
                *(uint64_t*)(Al + sw) = pk4(l0, l1, l2, l3);
            }
            ps.x += __shfl_xor_sync(0xffffffffu, ps.x, 8);
            ps.y += __shfl_xor_sync(0xffffffffu, ps.y, 8);
            ps.z += __shfl_xor_sync(0xffffffffu, ps.z, 8);
            ps.w += __shfl_xor_sync(0xffffffffu, ps.w, 8);
            ps.x += __shfl_xor_sync(0xffffffffu, ps.x, 16);
            ps.y += __shfl_xor_sync(0xffffffffu, ps.y, 16);
            ps.z += __shfl_xor_sync(0xffffffffu, ps.z, 16);
            ps.w += __shfl_xor_sync(0xffffffffu, ps.w, 16);
            if (lane < 8) sredc[wid][lane] = ps;
        }

        // ---- B conversion: B[n][k] = W1[kc+k][n] hi/lo ----
        #pragma unroll
        for (int q = 0; q < 16; q++) {
            int idx = q * 256 + tid;
            int n = idx & 127, k = idx >> 7;
            float v = W1[(size_t)(kc + k)*Hdim + n];
            __nv_bfloat16 h, l;
            split_bf16(v, h, l);
            uint32_t off = (uint32_t)(n * 64 + k * 2);
            uint32_t sw = off ^ (((uint32_t)(n & 7)) << 4);
            *(__nv_bfloat16*)(Bh + sw) = h;
            *(__nv_bfloat16*)(Bl + sw) = l;
        }
        __syncthreads();

        // colsum finalize for this chunk's 32 channels (fixed order)
        if (tid < 32) {
            float s = 0.f;
            #pragma unroll
            for (int w = 0; w < 8; w++) {
                const float* f = (const float*)&sredc[w][tid >> 2];
                s += f[tid & 3];
            }
            g_Tpart[(size_t)blockIdx.x * Cdim + kc + tid] = s;
        }

        // ---- mma compute: 2 k16 steps ----
        #pragma unroll
        for (int ks = 0; ks < 2; ks++) {
            uint32_t ahf[2][4], alf[2][4], bhf[8][2], blf[8][2];
            #pragma unroll
            for (int mf = 0; mf < 2; mf++) {
                int subm = lane >> 3, r = lane & 7;
                int m = wm*32 + mf*16 + ((subm & 1) << 3) + r;
                int kb = ks*16 + ((subm & 2) << 2);
                uint32_t off = (uint32_t)(m * 64 + kb * 2)
                             ^ (((uint32_t)(m & 7)) << 4);
                LDSM4(ahf[mf][0], ahf[mf][1], ahf[mf][2], ahf[mf][3], ah_b + off);
                LDSM4(alf[mf][0], alf[mf][1], alf[mf][2], alf[mf][3], al_b + off);
            }
            #pragma unroll
            for (int nf2 = 0; nf2 < 4; nf2++) {
                int grp = lane >> 3, r = lane & 7;
                int n = wn*64 + nf2*16 + ((grp & 2) << 2) + r;
                int kb = ks*16 + ((grp & 1) << 3);
                uint32_t off = (uint32_t)(n * 64 + kb * 2)
                             ^ (((uint32_t)(n & 7)) << 4);
                LDSM4(bhf[nf2*2][0], bhf[nf2*2][1],
                      bhf[nf2*2+1][0], bhf[nf2*2+1][1], bh_b + off);
                LDSM4(blf[nf2*2][0], blf[nf2*2][1],
                      blf[nf2*2+1][0], blf[nf2*2+1][1], bl_b + off);
            }
            // pass 1: hi*hi, pass 2: lo*hi, pass 3: hi*lo (fixed order)
            #pragma unroll
            for (int mf = 0; mf < 2; mf++)
                #pragma unroll
                for (int nf = 0; nf < 8; nf++)
                    MMA16816(acc[mf][nf], ahf[mf], bhf[nf]);
            #pragma unroll
            for (int mf = 0; mf < 2; mf++)
                #pragma unroll
                for (int nf = 0; nf < 8; nf++)
                    MMA16816(acc[mf][nf], alf[mf], bhf[nf]);
            #pragma unroll
            for (int mf = 0; mf < 2; mf++)
                #pragma unroll
                for (int nf = 0; nf < 8; nf++)
                    MMA16816(acc[mf][nf], ahf[mf], blf[nf]);
        }
    }

    // ---- epilogue: h = tanh(u + b1), s = sum h*W2, deterministic reduce ----
    float p[2][2] = {{0.f, 0.f}, {0.f, 0.f}};
    #pragma unroll
    for (int mf = 0; mf < 2; mf++)
        #pragma unroll
        for (int nf = 0; nf < 8; nf++) {
            int n0 = wn*64 + nf*8 + ((lane & 3) << 1);
            float b1a = b1s[n0], w2a = w2s[n0];
            float b1b = b1s[n0 + 1], w2b = w2s[n0 + 1];
            p[mf][0] += tanhf(acc[mf][nf][0] + b1a) * w2a
                      + tanhf(acc[mf][nf][1] + b1b) * w2b;
            p[mf][1] += tanhf(acc[mf][nf][2] + b1a) * w2a
                      + tanhf(acc[mf][nf][3] + b1b) * w2b;
        }
    #pragma unroll
    for (int mf = 0; mf < 2; mf++)
        #pragma unroll
        for (int h = 0; h < 2; h++) {
            p[mf][h] += __shfl_xor_sync(0xffffffffu, p[mf][h], 1);
            p[mf][h] += __shfl_xor_sync(0xffffffffu, p[mf][h], 2);
        }
    __syncthreads();
    if ((lane & 3) == 0) {
        #pragma unroll
        for (int mf = 0; mf < 2; mf++)
            #pragma unroll
            for (int h = 0; h < 2; h++)
                sredE[wm*32 + mf*16 + h*8 + (lane >> 2)][wn] = p[mf][h];
    }
    __syncthreads();
    if (tid < 128)
        g_e[m0 + tid] = expf(sredE[tid][0] + sredE[tid][1] + b2[0]);
}

// ---------------- mid: reduce T + compute 1/denom ----------------
__global__ void __launch_bounds__(256) k_mid() {
    int bid = blockIdx.x;
    int tid = threadIdx.x;
    if (bid < 4) {
        int b = bid, c = tid;
        double s = 0.0;
        #pragma unroll
        for (int ch = 0; ch < 32; ch++)
            s += (double)g_Tpart[(size_t)(b*32 + ch)*Cdim + c];
        g_T[b*Cdim + c] = (float)s;
    } else {
        int g = (bid - 4) * 256 + tid;
        int b = g >> 12;
        int i = g & (Ktok - 1);
        int jlo = max(i - RAD, 0), jhi = min(i + RAD, Ktok - 1);
        float s = (float)(Ktok - (jhi - jlo + 1));
        const float* ep = g_e + ((size_t)b << 12);
        #pragma unroll
        for (int j = 0; j < 2*RAD + 1; j++) {
            int jj = jlo + j;
            if (jj <= jhi) s += ep[jj];
        }
        g_inv[g] = 1.0f / s;
    }
}

// ---------------- fused output: weighted + weights interleaved 1:2 --------
__global__ void __launch_bounds__(256) k_fused(const float* __restrict__ x,
                                               float* __restrict__ wout,
                                               float* __restrict__ outw) {
    __shared__ float xs[(IBLK + 2*RAD) * Cdim];
    __shared__ float em1[32];
    __shared__ float invs[IBLK];

    int bid = blockIdx.x;
    int tid = threadIdx.x;
    int g3 = bid % 3;
    int q  = bid / 3;

    if (g3 != 0) {
        int chunk = q * 2 + (g3 - 1);
        int r0 = chunk * WROWS;
        int b = r0 >> 12, i0 = r0 & (Ktok - 1);
        int jlo0 = max(i0 - RAD, 0);
        int jhi0 = min(i0 + WROWS - 1 + RAD, Ktok - 1);
        int n = jhi0 - jlo0 + 1;
        float* sev  = xs;
        float* sinv = xs + 32;
        if (tid < n)     sev[tid]  = g_e[((size_t)b << 12) + jlo0 + tid];
        if (tid < WROWS) sinv[tid] = g_inv[r0 + tid];
        __syncthreads();

        #pragma unroll
        for (int ii = 0; ii < WROWS; ii++) {
            int i = i0 + ii;
            float inv = sinv[ii];
            int jlo = max(i - RAD, 0), jhi = min(i + RAD, Ktok - 1);
            float* row = wout + (size_t)(r0 + ii) * Ktok;
            float4 v4 = make_float4(inv, inv, inv, inv);
            #pragma unroll
            for (int q2 = 0; q2 < 4; q2++) {
                int jj = (q2 << 10) + (tid << 2);
                float4 t = v4;
                if (jj + 3 >= jlo && jj <= jhi) {
                    if (jj + 0 >= jlo && jj + 0 <= jhi) t.x = sev[jj + 0 - jlo0] * inv;
                    if (jj + 1 >= jlo && jj + 1 <= jhi) t.y = sev[jj + 1 - jlo0] * inv;
                    if (jj + 2 >= jlo && jj + 2 <= jhi) t.z = sev[jj + 2 - jlo0] * inv;
                    if (jj + 3 >= jlo && jj + 3 <= jhi) t.w = sev[jj + 3 - jlo0] * inv;
                }
                __stcs((float4*)&row[jj], t);
            }
        }
    } else {
        int b = q >> 8;
        int i0 = (q & 255) << 4;
        int jlo = max(i0 - RAD, 0);
        int jhi = min(i0 + IBLK - 1 + RAD, Ktok - 1);
        int n = jhi - jlo + 1;

        const float* xb = x + (((size_t)b << 12) + jlo) * Cdim;
        for (int idx = tid; idx < n * Cdim; idx += 256)
            xs[idx] = xb[idx];
        if (tid < n)    em1[tid]  = g_e[((size_t)b << 12) + jlo + tid] - 1.0f;
        if (tid < IBLK) invs[tid] = g_inv[((size_t)b << 12) + i0 + tid];
        float Tc = g_T[b * Cdim + tid];
        __syncthreads();

        int c = tid;
        float* op = outw + (((size_t)b << 12) + i0) * Cdim + c;
        #pragma unroll
        for (int ii = 0; ii < IBLK; ii++) {
            int i = i0 + ii;
            int lo = max(i - RAD, 0) - jlo;
            int hi = min(i + RAD, Ktok - 1) - jlo;
            float acc = Tc;
            for (int r = lo; r <= hi; r++) acc += em1[r] * xs[r * Cdim + c];
            __stcs(&op[(size_t)ii * Cdim], acc * invs[ii]);
        }
    }
}

// ---------------- launch ----------------
extern "C" void kernel_launch(void* const* d_in, const int* in_sizes, int n_in,
                              void* d_out, int out_size) {
    (void)in_sizes; (void)n_in; (void)out_size;
    const float* x  = (const float*)d_in[0];
    const float* W1 = (const float*)d_in[1];
    const float* b1 = (const float*)d_in[2];
    const float* W2 = (const float*)d_in[3];
    const float* b2 = (const float*)d_in[4];

    float* out_weighted = (float*)d_out;
    float* out_weights  = (float*)d_out + (size_t)NTOK * Cdim;

    k_mma  <<<NMMA,            256>>>(x, W1, b1, W2, b2);
    k_mid  <<<4 + NTOK / 256,  256>>>();
    k_fused<<<NWBLK + NWTBLK,  256>>>(x, out_weights, out_weighted);
}

// round 9
// speedup vs baseline: 3.0509x; 1.1458x over previous
#include <cuda_runtime.h>
#include <cuda_bf16.h>
#include <math.h>
#include <stdint.h>

#define RAD   5
#define Bz    4
#define Ktok  4096
#define Cdim  256
#define Hdim  128
#define NTOK  (Bz*Ktok)           // 16384
#define IBLK  16                  // rows per weighted block
#define NWBLK (NTOK/IBLK)         // 1024 weighted blocks
#define WROWS 8                   // rows per weights block
#define NWTBLK (NTOK/WROWS)       // 2048 weights blocks
#define NMMA  (NTOK/128)          // 128 MMA CTAs
#define CHPB  (NMMA/Bz)           // 32 chunks per batch

// ---------------- scratch ----------------
__device__ float  g_Tpart[NMMA*Cdim];    // per-CTA (128-token) col sums
__device__ float  g_e[NTOK];
__device__ __nv_bfloat16 g_W1h[Cdim*Hdim];   // W1 bf16 hi, [n][k] n-major
__device__ __nv_bfloat16 g_W1l[Cdim*Hdim];   // W1 bf16 lo

// ---------------- helpers ----------------
__device__ __forceinline__ uint32_t smem_u32(const void* p) {
    return (uint32_t)__cvta_generic_to_shared(p);
}
#define LDSM4(r0, r1, r2, r3, addr) \
    asm volatile("ldmatrix.sync.aligned.m8n8.x4.shared.b16 {%0,%1,%2,%3}, [%4];" \
        : "=r"(r0), "=r"(r1), "=r"(r2), "=r"(r3) : "r"(addr))
#define MMA16816(d, a, b) \
    asm volatile("mma.sync.aligned.m16n8k16.row.col.f32.bf16.bf16.f32 " \
        "{%0,%1,%2,%3}, {%4,%5,%6,%7}, {%8,%9}, {%0,%1,%2,%3};" \
        : "+f"((d)[0]), "+f"((d)[1]), "+f"((d)[2]), "+f"((d)[3]) \
        : "r"((a)[0]), "r"((a)[1]), "r"((a)[2]), "r"((a)[3]), \
          "r"((b)[0]), "r"((b)[1]))

__device__ __forceinline__ uint64_t pk4(__nv_bfloat16 a, __nv_bfloat16 b,
                                        __nv_bfloat16 c, __nv_bfloat16 d) {
    uint16_t ua = *(uint16_t*)&a, ub = *(uint16_t*)&b;
    uint16_t uc = *(uint16_t*)&c, ud = *(uint16_t*)&d;
    return (uint64_t)ua | ((uint64_t)ub << 16) | ((uint64_t)uc << 32) | ((uint64_t)ud << 48);
}
__device__ __forceinline__ void split_bf16(float v, __nv_bfloat16& h, __nv_bfloat16& l) {
    h = __float2bfloat16(v);
    l = __float2bfloat16(v - __bfloat162float(h));
}

// ---------------- prep: W1 -> bf16 hi/lo, transposed to [n][k] ------------
__global__ void __launch_bounds__(256) k_prep(const float* __restrict__ W1) {
    int idx = blockIdx.x * 256 + threadIdx.x;   // 0..32767
    int k = idx >> 7, n = idx & 127;            // coalesced read of W1[k][n]
    float v = W1[idx];
    __nv_bfloat16 h, l;
    split_bf16(v, h, l);
    g_W1h[n * Cdim + k] = h;
    g_W1l[n * Cdim + k] = l;
}

// ---------------- MLP via warp-mma bf16 split x3 + colsum ----------------
// Per CTA: 128 tokens(M) x 128 hidden(N), K=256 in 8 chunks of 32, pipelined.
__global__ void __launch_bounds__(256, 1)
k_mma(const float* __restrict__ x, const float* __restrict__ b1,
      const float* __restrict__ W2, const float* __restrict__ b2) {
    __shared__ __align__(16) char Ah[128*64];   // 8KB each
    __shared__ __align__(16) char Al[128*64];
    __shared__ __align__(16) char Bh[128*64];
    __shared__ __align__(16) char Bl[128*64];
    __shared__ float4 sredc[8][8];
    __shared__ float  sredE[128][2];
    __shared__ float  b1s[Hdim], w2s[Hdim];

    int tid = threadIdx.x;
    int wid = tid >> 5, lane = tid & 31;
    int wm = wid & 3, wn = wid >> 2;
    int m0 = blockIdx.x * 128;

    if (tid < Hdim) { b1s[tid] = b1[tid]; w2s[tid] = W2[tid]; }

    uint32_t ah_b = smem_u32(Ah), al_b = smem_u32(Al);
    uint32_t bh_b = smem_u32(Bh), bl_b = smem_u32(Bl);

    float acc[2][8][4];
    #pragma unroll
    for (int mf = 0; mf < 2; mf++)
        #pragma unroll
        for (int nf = 0; nf < 8; nf++)
            #pragma unroll
            for (int c = 0; c < 4; c++) acc[mf][nf][c] = 0.f;

    // ---- prefetch chunk 0 ----
    int f8 = tid & 7;               // A: float4 slot in 32-k chunk row
    int bn = tid >> 2;              // B slot0: n = tid>>2 (we do 2 slots)
    float4 xv[4];
    uint4  bhv[2], blv[2];
    {
        #pragma unroll
        for (int q = 0; q < 4; q++) {
            int row = q * 32 + (tid >> 3);
            xv[q] = *(const float4*)&x[(size_t)(m0 + row)*Cdim + f8*4];
        }
        #pragma unroll
        for (int j = 0; j < 2; j++) {
            int idx = j * 256 + tid;          // 0..511
            int n = idx >> 2, kq = (idx & 3) * 8;
            bhv[j] = *(const uint4*)&g_W1h[(size_t)n*Cdim + kq];
            blv[j] = *(const uint4*)&g_W1l[(size_t)n*Cdim + kq];
        }
    }

    for (int ck = 0; ck < 8; ck++) {
        int kc = ck * 32;
        __syncthreads();   // tiles + sredc reusable (prev chunk mma/finalize done)

        // ---- store phase: convert A, raw-store B, colsum partial ----
        float4 ps = make_float4(0.f, 0.f, 0.f, 0.f);
        #pragma unroll
        for (int q = 0; q < 4; q++) {
            int row = q * 32 + (tid >> 3);
            float4 v = xv[q];
            ps.x += v.x; ps.y += v.y; ps.z += v.z; ps.w += v.w;
            __nv_bfloat16 h0,l0,h1,l1,h2,l2,h3,l3;
            split_bf16(v.x, h0, l0); split_bf16(v.y, h1, l1);
            split_bf16(v.z, h2, l2); split_bf16(v.w, h3, l3);
            uint32_t off = (uint32_t)(row * 64 + f8 * 8);
            uint32_t sw = off ^ (((uint32_t)(row & 7)) << 4);
            *(uint64_t*)(Ah + sw) = pk4(h0, h1, h2, h3);
            *(uint64_t*)(Al + sw) = pk4(l0, l1, l2, l3);
        }
        #pragma unroll
        for (int j = 0; j < 2; j++) {
            int idx = j * 256 + tid;
            int n = idx >> 2, kq = (idx & 3) * 8;
            uint32_t off = (uint32_t)(n * 64 + kq * 2);
            uint32_t sw = off ^ (((uint32_t)(n & 7)) << 4);
            *(uint4*)(Bh + sw) = bhv[j];
            *(uint4*)(Bl + sw) = blv[j];
        }
        ps.x += __shfl_xor_sync(0xffffffffu, ps.x, 8);
        ps.y += __shfl_xor_sync(0xffffffffu, ps.y, 8);
        ps.z += __shfl_xor_sync(0xffffffffu, ps.z, 8);
        ps.w += __shfl_xor_sync(0xffffffffu, ps.w, 8);
        ps.x += __shfl_xor_sync(0xffffffffu, ps.x, 16);
        ps.y += __shfl_xor_sync(0xffffffffu, ps.y, 16);
        ps.z += __shfl_xor_sync(0xffffffffu, ps.z, 16);
        ps.w += __shfl_xor_sync(0xffffffffu, ps.w, 16);
        if (lane < 8) sredc[wid][lane] = ps;
        __syncthreads();

        // colsum finalize (fixed order over 8 warps)
        if (tid < 32) {
            float s = 0.f;
            #pragma unroll
            for (int w = 0; w < 8; w++) {
                const float* f = (const float*)&sredc[w][tid >> 2];
                s += f[tid & 3];
            }
            g_Tpart[(size_t)blockIdx.x * Cdim + kc + tid] = s;
        }

        // ---- prefetch chunk ck+1 (latency hides under mma below) ----
        if (ck < 7) {
            int kn = kc + 32;
            #pragma unroll
            for (int q = 0; q < 4; q++) {
                int row = q * 32 + (tid >> 3);
                xv[q] = *(const float4*)&x[(size_t)(m0 + row)*Cdim + kn + f8*4];
            }
            #pragma unroll
            for (int j = 0; j < 2; j++) {
                int idx = j * 256 + tid;
                int n = idx >> 2, kq = (idx & 3) * 8;
                bhv[j] = *(const uint4*)&g_W1h[(size_t)n*Cdim + kn + kq];
                blv[j] = *(const uint4*)&g_W1l[(size_t)n*Cdim + kn + kq];
            }
        }

        // ---- mma: 2 k16 steps, 3 passes ----
        #pragma unroll
        for (int ks = 0; ks < 2; ks++) {
            uint32_t ahf[2][4], alf[2][4], bhf[8][2], blf[8][2];
            #pragma unroll
            for (int mf = 0; mf < 2; mf++) {
                int subm = lane >> 3, r = lane & 7;
                int m = wm*32 + mf*16 + ((subm & 1) << 3) + r;
                int kb = ks*16 + ((subm & 2) << 2);
                uint32_t off = (uint32_t)(m * 64 + kb * 2)
                             ^ (((uint32_t)(m & 7)) << 4);
                LDSM4(ahf[mf][0], ahf[mf][1], ahf[mf][2], ahf[mf][3], ah_b + off);
                LDSM4(alf[mf][0], alf[mf][1], alf[mf][2], alf[mf][3], al_b + off);
            }
            #pragma unroll
            for (int nf2 = 0; nf2 < 4; nf2++) {
                int grp = lane >> 3, r = lane & 7;
                int n = wn*64 + nf2*16 + ((grp & 2) << 2) + r;
                int kb = ks*16 + ((grp & 1) << 3);
                uint32_t off = (uint32_t)(n * 64 + kb * 2)
                             ^ (((uint32_t)(n & 7)) << 4);
                LDSM4(bhf[nf2*2][0], bhf[nf2*2][1],
                      bhf[nf2*2+1][0], bhf[nf2*2+1][1], bh_b + off);
                LDSM4(blf[nf2*2][0], blf[nf2*2][1],
                      blf[nf2*2+1][0], blf[nf2*2+1][1], bl_b + off);
            }
            #pragma unroll
            for (int mf = 0; mf < 2; mf++)
                #pragma unroll
                for (int nf = 0; nf < 8; nf++)
                    MMA16816(acc[mf][nf], ahf[mf], bhf[nf]);
            #pragma unroll
            for (int mf = 0; mf < 2; mf++)
                #pragma unroll
                for (int nf = 0; nf < 8; nf++)
                    MMA16816(acc[mf][nf], alf[mf], bhf[nf]);
            #pragma unroll
            for (int mf = 0; mf < 2; mf++)
                #pragma unroll
                for (int nf = 0; nf < 8; nf++)
                    MMA16816(acc[mf][nf], ahf[mf], blf[nf]);
        }
    }

    // ---- epilogue ----
    float p[2][2] = {{0.f, 0.f}, {0.f, 0.f}};
    #pragma unroll
    for (int mf = 0; mf < 2; mf++)
        #pragma unroll
        for (int nf = 0; nf < 8; nf++) {
            int n0 = wn*64 + nf*8 + ((lane & 3) << 1);
            float b1a = b1s[n0], w2a = w2s[n0];
            float b1b = b1s[n0 + 1], w2b = w2s[n0 + 1];
            p[mf][0] += tanhf(acc[mf][nf][0] + b1a) * w2a
                      + tanhf(acc[mf][nf][1] + b1b) * w2b;
            p[mf][1] += tanhf(acc[mf][nf][2] + b1a) * w2a
                      + tanhf(acc[mf][nf][3] + b1b) * w2b;
        }
    #pragma unroll
    for (int mf = 0; mf < 2; mf++)
        #pragma unroll
        for (int h = 0; h < 2; h++) {
            p[mf][h] += __shfl_xor_sync(0xffffffffu, p[mf][h], 1);
            p[mf][h] += __shfl_xor_sync(0xffffffffu, p[mf][h], 2);
        }
    __syncthreads();
    if ((lane & 3) == 0) {
        #pragma unroll
        for (int mf = 0; mf < 2; mf++)
            #pragma unroll
            for (int h = 0; h < 2; h++)
                sredE[wm*32 + mf*16 + h*8 + (lane >> 2)][wn] = p[mf][h];
    }
    __syncthreads();
    if (tid < 128)
        g_e[m0 + tid] = expf(sredE[tid][0] + sredE[tid][1] + b2[0]);
}

// ---------------- fused output (k_mid folded in, fp32) --------------------
__global__ void __launch_bounds__(256) k_fused(const float* __restrict__ x,
                                               float* __restrict__ wout,
                                               float* __restrict__ outw) {
    __shared__ float xs[(IBLK + 2*RAD) * Cdim];
    __shared__ float em1[32];
    __shared__ float invs[IBLK];

    int bid = blockIdx.x;
    int tid = threadIdx.x;
    int g3 = bid % 3;
    int q  = bid / 3;

    if (g3 != 0) {
        // ---- weights fill: 8 rows per block ----
        int chunk = q * 2 + (g3 - 1);
        int r0 = chunk * WROWS;
        int b = r0 >> 12, i0 = r0 & (Ktok - 1);
        int jlo0 = max(i0 - RAD, 0);
        int jhi0 = min(i0 + WROWS - 1 + RAD, Ktok - 1);
        int n = jhi0 - jlo0 + 1;
        float* sev  = xs;
        float* sinv = xs + 32;
        if (tid < n) sev[tid] = g_e[((size_t)b << 12) + jlo0 + tid];
        __syncthreads();
        if (tid < WROWS) {
            int i = i0 + tid;
            int jl = max(i - RAD, 0), jh = min(i + RAD, Ktok - 1);
            float s = (float)(Ktok - (jh - jl + 1));
            for (int j = jl; j <= jh; j++) s += sev[j - jlo0];
            sinv[tid] = 1.0f / s;
        }
        __syncthreads();

        #pragma unroll
        for (int ii = 0; ii < WROWS; ii++) {
            int i = i0 + ii;
            float inv = sinv[ii];
            int jlo = max(i - RAD, 0), jhi = min(i + RAD, Ktok - 1);
            float* row = wout + (size_t)(r0 + ii) * Ktok;
            float4 v4 = make_float4(inv, inv, inv, inv);
            #pragma unroll
            for (int q2 = 0; q2 < 4; q2++) {
                int jj = (q2 << 10) + (tid << 2);
                float4 t = v4;
                if (jj + 3 >= jlo && jj <= jhi) {
                    if (jj + 0 >= jlo && jj + 0 <= jhi) t.x = sev[jj + 0 - jlo0] * inv;
                    if (jj + 1 >= jlo && jj + 1 <= jhi) t.y = sev[jj + 1 - jlo0] * inv;
                    if (jj + 2 >= jlo && jj + 2 <= jhi) t.z = sev[jj + 2 - jlo0] * inv;
                    if (jj + 3 >= jlo && jj + 3 <= jhi) t.w = sev[jj + 3 - jlo0] * inv;
                }
                __stcs((float4*)&row[jj], t);
            }
        }
    } else {
        // ---- weighted rows ----
        int b = q >> 8;
        int i0 = (q & 255) << 4;
        int jlo = max(i0 - RAD, 0);
        int jhi = min(i0 + IBLK - 1 + RAD, Ktok - 1);
        int n = jhi - jlo + 1;

        const float* xb = x + (((size_t)b << 12) + jlo) * Cdim;
        for (int idx = tid; idx < n * Cdim; idx += 256)
            xs[idx] = xb[idx];
        if (tid < n) em1[tid] = g_e[((size_t)b << 12) + jlo + tid];
        __syncthreads();

        // local 1/denom (ascending order)
        if (tid < IBLK) {
            int i = i0 + tid;
            int jl = max(i - RAD, 0), jh = min(i + RAD, Ktok - 1);
            float s = (float)(Ktok - (jh - jl + 1));
            for (int j = jl; j <= jh; j++) s += em1[j - jlo];
            invs[tid] = 1.0f / s;
        }
        // T self-reduce in fp32 (fixed order over 32 chunks, L2-resident)
        float Tc = 0.f;
        #pragma unroll
        for (int ch = 0; ch < CHPB; ch++)
            Tc += g_Tpart[(size_t)(b*CHPB + ch)*Cdim + tid];
        __syncthreads();
        if (tid < n) em1[tid] -= 1.0f;
        __syncthreads();

        int c = tid;
        float* op = outw + (((size_t)b << 12) + i0) * Cdim + c;
        #pragma unroll
        for (int ii = 0; ii < IBLK; ii++) {
            int i = i0 + ii;
            int lo = max(i - RAD, 0) - jlo;
            int hi = min(i + RAD, Ktok - 1) - jlo;
            float acc = Tc;
            for (int r = lo; r <= hi; r++) acc += em1[r] * xs[r * Cdim + c];
            __stcs(&op[(size_t)ii * Cdim], acc * invs[ii]);
        }
    }
}

// ---------------- launch ----------------
extern "C" void kernel_launch(void* const* d_in, const int* in_sizes, int n_in,
                              void* d_out, int out_size) {
    (void)in_sizes; (void)n_in; (void)out_size;
    const float* x  = (const float*)d_in[0];
    const float* W1 = (const float*)d_in[1];
    const float* b1 = (const float*)d_in[2];
    const float* W2 = (const float*)d_in[3];
    const float* b2 = (const float*)d_in[4];

    float* out_weighted = (float*)d_out;
    float* out_weights  = (float*)d_out + (size_t)NTOK * Cdim;

    k_prep <<<Cdim*Hdim/256,  256>>>(W1);
    k_mma  <<<NMMA,           256>>>(x, b1, W2, b2);
    k_fused<<<NWBLK + NWTBLK, 256>>>(x, out_weights, out_weighted);
}